// round 5
// baseline (speedup 1.0000x reference)
#include <cuda_runtime.h>

// Hyperelasticity: closed-form Neo-Hookean stress.
// PK1 = MU*F + (LAM*lnJ - MU)*F^{-T};  PK2 = sym(F^{-1} PK1);  sig = sym(PK1 F^T)/J
//
// Warp-autonomous version: each warp owns 32 points and stages the 9-float
// transpose through its private smem slice with __syncwarp only -- no block
// barriers, so warps free-run and stagger their DRAM demand.
#define MU  1.0f
#define LAM 1.0f
#define BS  128
#define WPB (BS / 32)

__device__ __forceinline__ void compute_point(const float* __restrict__ Fp,
                                              float* __restrict__ o1,
                                              float* __restrict__ o2,
                                              float* __restrict__ o3)
{
    float a = Fp[0], b = Fp[1], c = Fp[2];
    float d = Fp[3], e = Fp[4], f = Fp[5];
    float g = Fp[6], h = Fp[7], i = Fp[8];

    // cofactors: F^{-T} = C/J, F^{-1} = C^T/J
    float C00 = fmaf(e, i, -f * h);
    float C01 = fmaf(f, g, -d * i);
    float C02 = fmaf(d, h, -e * g);
    float C10 = fmaf(c, h, -b * i);
    float C11 = fmaf(a, i, -c * g);
    float C12 = fmaf(b, g, -a * h);
    float C20 = fmaf(b, f, -c * e);
    float C21 = fmaf(c, d, -a * f);
    float C22 = fmaf(a, e, -b * d);

    float J   = a * C00 + b * C01 + c * C02;
    float rJ  = __frcp_rn(J);
    float lnJ = __logf(J);

    float s = (LAM * lnJ - MU) * rJ;
    float P00 = fmaf(s, C00, MU * a);
    float P01 = fmaf(s, C01, MU * b);
    float P02 = fmaf(s, C02, MU * c);
    float P10 = fmaf(s, C10, MU * d);
    float P11 = fmaf(s, C11, MU * e);
    float P12 = fmaf(s, C12, MU * f);
    float P20 = fmaf(s, C20, MU * g);
    float P21 = fmaf(s, C21, MU * h);
    float P22 = fmaf(s, C22, MU * i);

    // Finv = C^T/J
    float I00 = C00 * rJ, I01 = C10 * rJ, I02 = C20 * rJ;
    float I10 = C01 * rJ, I11 = C11 * rJ, I12 = C21 * rJ;
    float I20 = C02 * rJ, I21 = C12 * rJ, I22 = C22 * rJ;

    float M00 = I00*P00 + I01*P10 + I02*P20;
    float M01 = I00*P01 + I01*P11 + I02*P21;
    float M02 = I00*P02 + I01*P12 + I02*P22;
    float M10 = I10*P00 + I11*P10 + I12*P20;
    float M11 = I10*P01 + I11*P11 + I12*P21;
    float M12 = I10*P02 + I11*P12 + I12*P22;
    float M20 = I20*P00 + I21*P10 + I22*P20;
    float M21 = I20*P01 + I21*P11 + I22*P21;
    float M22 = I20*P02 + I21*P12 + I22*P22;

    float S01 = 0.5f * (M01 + M10);
    float S02 = 0.5f * (M02 + M20);
    float S12 = 0.5f * (M12 + M21);

    float T00 = P00*a + P01*b + P02*c;
    float T01 = P00*d + P01*e + P02*f;
    float T02 = P00*g + P01*h + P02*i;
    float T10 = P10*a + P11*b + P12*c;
    float T11 = P10*d + P11*e + P12*f;
    float T12 = P10*g + P11*h + P12*i;
    float T20 = P20*a + P21*b + P22*c;
    float T21 = P20*d + P21*e + P22*f;
    float T22 = P20*g + P21*h + P22*i;

    o1[0] = P00; o1[1] = P01; o1[2] = P02;
    o1[3] = P10; o1[4] = P11; o1[5] = P12;
    o1[6] = P20; o1[7] = P21; o1[8] = P22;

    o2[0] = M00; o2[1] = S01; o2[2] = S02;
    o2[3] = S01; o2[4] = M11; o2[5] = S12;
    o2[6] = S02; o2[7] = S12; o2[8] = M22;

    float G01 = 0.5f * (T01 + T10) * rJ;
    float G02 = 0.5f * (T02 + T20) * rJ;
    float G12 = 0.5f * (T12 + T21) * rJ;
    o3[0] = T00 * rJ; o3[1] = G01;      o3[2] = G02;
    o3[3] = G01;      o3[4] = T11 * rJ; o3[5] = G12;
    o3[6] = G02;      o3[7] = G12;      o3[8] = T22 * rJ;
}

__global__ __launch_bounds__(BS)
void hyper_kernel(const float* __restrict__ Fin,
                  float* __restrict__ out,
                  int n)
{
    // per-warp private staging slices: 288 floats (32 points x 9)
    __shared__ __align__(16) float sIn[WPB][288];
    __shared__ __align__(16) float sOut[WPB][3][288];

    const int warp = threadIdx.x >> 5;
    const int lane = threadIdx.x & 31;
    const int base = blockIdx.x * BS + warp * 32;   // warp's first point
    const size_t nn = (size_t)n * 9;

    if (base + 32 <= n) {
        // ---- load 32 points = 72 float4, coalesced ----
        const float4* src = (const float4*)(Fin + (size_t)base * 9);
        float4* s4 = (float4*)sIn[warp];
        s4[lane]      = src[lane];
        s4[lane + 32] = src[lane + 32];
        if (lane < 8) s4[lane + 64] = src[lane + 64];
        __syncwarp();

        // ---- transpose read: stride 9, coprime with 32 banks ----
        float Fp[9], o1[9], o2[9], o3[9];
        #pragma unroll
        for (int k = 0; k < 9; k++) Fp[k] = sIn[warp][lane * 9 + k];

        compute_point(Fp, o1, o2, o3);

        #pragma unroll
        for (int k = 0; k < 9; k++) {
            sOut[warp][0][lane * 9 + k] = o1[k];
            sOut[warp][1][lane * 9 + k] = o2[k];
            sOut[warp][2][lane * 9 + k] = o3[k];
        }
        __syncwarp();

        // ---- store 3 regions x 72 float4, coalesced ----
        #pragma unroll
        for (int r = 0; r < 3; r++) {
            float4* dst = (float4*)(out + r * nn + (size_t)base * 9);
            const float4* q = (const float4*)sOut[warp][r];
            dst[lane]      = q[lane];
            dst[lane + 32] = q[lane + 32];
            if (lane < 8) dst[lane + 64] = q[lane + 64];
        }
    } else {
        // ---- tail warp: scalar guarded path ----
        int idx = base + lane;
        if (idx < n) {
            float Fp[9], o1[9], o2[9], o3[9];
            #pragma unroll
            for (int k = 0; k < 9; k++) Fp[k] = Fin[(size_t)idx * 9 + k];
            compute_point(Fp, o1, o2, o3);
            #pragma unroll
            for (int k = 0; k < 9; k++) {
                out[(size_t)idx * 9 + k]          = o1[k];
                out[nn + (size_t)idx * 9 + k]     = o2[k];
                out[2 * nn + (size_t)idx * 9 + k] = o3[k];
            }
        }
    }
}

extern "C" void kernel_launch(void* const* d_in, const int* in_sizes, int n_in,
                              void* d_out, int out_size)
{
    const float* F = (const float*)d_in[0];
    float* out = (float*)d_out;
    int n = in_sizes[0] / 9;

    int blocks = (n + BS - 1) / BS;
    hyper_kernel<<<blocks, BS>>>(F, out, n);
}

// round 6
// speedup vs baseline: 1.0100x; 1.0100x over previous
#include <cuda_runtime.h>

// Hyperelasticity: closed-form Neo-Hookean stress.
// PK1 = MU*F + (LAM*lnJ - MU)*F^{-T};  PK2 = sym(F^{-1} PK1);  sig = sym(PK1 F^T)/J
//
// Warp-autonomous, 64 points/warp in two sub-tiles with both sub-tiles'
// gmem loads issued up-front (2x MLP). Streaming loads (__ldcs) and
// streaming stores (__stcs). __syncwarp only -- no block barriers.
#define MU  1.0f
#define LAM 1.0f
#define BS  128
#define WPB (BS / 32)

__device__ __forceinline__ void compute_point(const float* __restrict__ Fp,
                                              float* __restrict__ o1,
                                              float* __restrict__ o2,
                                              float* __restrict__ o3)
{
    float a = Fp[0], b = Fp[1], c = Fp[2];
    float d = Fp[3], e = Fp[4], f = Fp[5];
    float g = Fp[6], h = Fp[7], i = Fp[8];

    // cofactors: F^{-T} = C/J, F^{-1} = C^T/J
    float C00 = fmaf(e, i, -f * h);
    float C01 = fmaf(f, g, -d * i);
    float C02 = fmaf(d, h, -e * g);
    float C10 = fmaf(c, h, -b * i);
    float C11 = fmaf(a, i, -c * g);
    float C12 = fmaf(b, g, -a * h);
    float C20 = fmaf(b, f, -c * e);
    float C21 = fmaf(c, d, -a * f);
    float C22 = fmaf(a, e, -b * d);

    float J   = a * C00 + b * C01 + c * C02;
    float rJ  = __frcp_rn(J);
    float lnJ = __logf(J);

    float s = (LAM * lnJ - MU) * rJ;
    float P00 = fmaf(s, C00, MU * a);
    float P01 = fmaf(s, C01, MU * b);
    float P02 = fmaf(s, C02, MU * c);
    float P10 = fmaf(s, C10, MU * d);
    float P11 = fmaf(s, C11, MU * e);
    float P12 = fmaf(s, C12, MU * f);
    float P20 = fmaf(s, C20, MU * g);
    float P21 = fmaf(s, C21, MU * h);
    float P22 = fmaf(s, C22, MU * i);

    // Finv = C^T/J
    float I00 = C00 * rJ, I01 = C10 * rJ, I02 = C20 * rJ;
    float I10 = C01 * rJ, I11 = C11 * rJ, I12 = C21 * rJ;
    float I20 = C02 * rJ, I21 = C12 * rJ, I22 = C22 * rJ;

    float M00 = I00*P00 + I01*P10 + I02*P20;
    float M01 = I00*P01 + I01*P11 + I02*P21;
    float M02 = I00*P02 + I01*P12 + I02*P22;
    float M10 = I10*P00 + I11*P10 + I12*P20;
    float M11 = I10*P01 + I11*P11 + I12*P21;
    float M12 = I10*P02 + I11*P12 + I12*P22;
    float M20 = I20*P00 + I21*P10 + I22*P20;
    float M21 = I20*P01 + I21*P11 + I22*P21;
    float M22 = I20*P02 + I21*P12 + I22*P22;

    float S01 = 0.5f * (M01 + M10);
    float S02 = 0.5f * (M02 + M20);
    float S12 = 0.5f * (M12 + M21);

    float T00 = P00*a + P01*b + P02*c;
    float T01 = P00*d + P01*e + P02*f;
    float T02 = P00*g + P01*h + P02*i;
    float T10 = P10*a + P11*b + P12*c;
    float T11 = P10*d + P11*e + P12*f;
    float T12 = P10*g + P11*h + P12*i;
    float T20 = P20*a + P21*b + P22*c;
    float T21 = P20*d + P21*e + P22*f;
    float T22 = P20*g + P21*h + P22*i;

    o1[0] = P00; o1[1] = P01; o1[2] = P02;
    o1[3] = P10; o1[4] = P11; o1[5] = P12;
    o1[6] = P20; o1[7] = P21; o1[8] = P22;

    o2[0] = M00; o2[1] = S01; o2[2] = S02;
    o2[3] = S01; o2[4] = M11; o2[5] = S12;
    o2[6] = S02; o2[7] = S12; o2[8] = M22;

    float G01 = 0.5f * (T01 + T10) * rJ;
    float G02 = 0.5f * (T02 + T20) * rJ;
    float G12 = 0.5f * (T12 + T21) * rJ;
    o3[0] = T00 * rJ; o3[1] = G01;      o3[2] = G02;
    o3[3] = G01;      o3[4] = T11 * rJ; o3[5] = G12;
    o3[6] = G02;      o3[7] = G12;      o3[8] = T22 * rJ;
}

// compute + stage one 32-point sub-tile from staged input, then flush
__device__ __forceinline__ void do_subtile(float* __restrict__ sIn,
                                           float* __restrict__ sOut,   // [3*288]
                                           float* __restrict__ out,
                                           size_t nn, long base, int lane)
{
    float Fp[9], o1[9], o2[9], o3[9];
    #pragma unroll
    for (int k = 0; k < 9; k++) Fp[k] = sIn[lane * 9 + k];

    compute_point(Fp, o1, o2, o3);

    #pragma unroll
    for (int k = 0; k < 9; k++) {
        sOut[lane * 9 + k]       = o1[k];
        sOut[288 + lane * 9 + k] = o2[k];
        sOut[576 + lane * 9 + k] = o3[k];
    }
}

__device__ __forceinline__ void flush_subtile(const float* __restrict__ sOut,
                                              float* __restrict__ out,
                                              size_t nn, long base, int lane)
{
    #pragma unroll
    for (int r = 0; r < 3; r++) {
        float4* dst = (float4*)(out + r * nn + (size_t)base * 9);
        const float4* q = (const float4*)(sOut + r * 288);
        __stcs(dst + lane,      q[lane]);
        __stcs(dst + lane + 32, q[lane + 32]);
        if (lane < 8) __stcs(dst + lane + 64, q[lane + 64]);
    }
}

__global__ __launch_bounds__(BS)
void hyper_kernel(const float* __restrict__ Fin,
                  float* __restrict__ out,
                  int n)
{
    __shared__ __align__(16) float sIn[WPB][288];        // 32 pts staged input
    __shared__ __align__(16) float sOut[WPB][3 * 288];   // 32 pts staged output

    const int warp = threadIdx.x >> 5;
    const int lane = threadIdx.x & 31;
    const long baseA = (long)blockIdx.x * (BS * 2) + warp * 64;  // 64 pts per warp
    const long baseB = baseA + 32;
    const size_t nn = (size_t)n * 9;

    float* sI = sIn[warp];
    float* sO = sOut[warp];

    if (baseA + 64 <= n) {
        const float4* srcA = (const float4*)(Fin + (size_t)baseA * 9);
        const float4* srcB = (const float4*)(Fin + (size_t)baseB * 9);

        // issue ALL gmem loads up-front: up to 4.5 LDG.128 in flight per lane
        float4 rA0 = __ldcs(srcA + lane);
        float4 rA1 = __ldcs(srcA + lane + 32);
        float4 rA2; if (lane < 8) rA2 = __ldcs(srcA + lane + 64);
        float4 rB0 = __ldcs(srcB + lane);
        float4 rB1 = __ldcs(srcB + lane + 32);
        float4 rB2; if (lane < 8) rB2 = __ldcs(srcB + lane + 64);

        float4* s4 = (float4*)sI;

        // ---- sub-tile A ----
        s4[lane] = rA0; s4[lane + 32] = rA1;
        if (lane < 8) s4[lane + 64] = rA2;
        __syncwarp();

        do_subtile(sI, sO, out, nn, baseA, lane);
        __syncwarp();                       // A input consumed, A outputs visible

        // stage B input while flushing A outputs
        s4[lane] = rB0; s4[lane + 32] = rB1;
        if (lane < 8) s4[lane + 64] = rB2;

        flush_subtile(sO, out, nn, baseA, lane);
        __syncwarp();                       // B staged, A out-buffer reads done

        // ---- sub-tile B ----
        do_subtile(sI, sO, out, nn, baseB, lane);
        __syncwarp();

        flush_subtile(sO, out, nn, baseB, lane);
    } else {
        // ---- tail: scalar guarded path for both sub-tiles ----
        #pragma unroll
        for (int s = 0; s < 2; s++) {
            long idx = baseA + s * 32 + lane;
            if (idx < n) {
                float Fp[9], o1[9], o2[9], o3[9];
                #pragma unroll
                for (int k = 0; k < 9; k++) Fp[k] = Fin[(size_t)idx * 9 + k];
                compute_point(Fp, o1, o2, o3);
                #pragma unroll
                for (int k = 0; k < 9; k++) {
                    out[(size_t)idx * 9 + k]          = o1[k];
                    out[nn + (size_t)idx * 9 + k]     = o2[k];
                    out[2 * nn + (size_t)idx * 9 + k] = o3[k];
                }
            }
        }
    }
}

extern "C" void kernel_launch(void* const* d_in, const int* in_sizes, int n_in,
                              void* d_out, int out_size)
{
    const float* F = (const float*)d_in[0];
    float* out = (float*)d_out;
    int n = in_sizes[0] / 9;

    int pts_per_block = BS * 2;     // 64 per warp, 4 warps
    int blocks = (n + pts_per_block - 1) / pts_per_block;
    hyper_kernel<<<blocks, BS>>>(F, out, n);
}

// round 7
// speedup vs baseline: 1.1669x; 1.1553x over previous
#include <cuda_runtime.h>
#include <cstdint>

// Hyperelasticity: closed-form Neo-Hookean stress.
// PK1 = MU*F + (LAM*lnJ - MU)*F^{-T};  PK2 = sym(F^{-1} PK1);  sig = sym(PK1 F^T)/J
//
// Warp-autonomous, 64 points/warp in two sub-tiles. Input prefetched with
// per-warp double-buffered cp.async.cg (MLP lives in the async pipe, not the
// register file). Streaming stores. __syncwarp only -- no block barriers.
#define MU  1.0f
#define LAM 1.0f
#define BS  128
#define WPB (BS / 32)

__device__ __forceinline__ uint32_t smem_u32(const void* p) {
    return (uint32_t)__cvta_generic_to_shared(p);
}
__device__ __forceinline__ void cp_async16(uint32_t dst, const void* src) {
    asm volatile("cp.async.cg.shared.global [%0], [%1], 16;\n" :: "r"(dst), "l"(src));
}
__device__ __forceinline__ void cp_commit() { asm volatile("cp.async.commit_group;\n"); }
__device__ __forceinline__ void cp_wait1()  { asm volatile("cp.async.wait_group 1;\n" ::: "memory"); }
__device__ __forceinline__ void cp_wait0()  { asm volatile("cp.async.wait_group 0;\n" ::: "memory"); }

__device__ __forceinline__ void compute_point(const float* __restrict__ Fp,
                                              float* __restrict__ o1,
                                              float* __restrict__ o2,
                                              float* __restrict__ o3)
{
    float a = Fp[0], b = Fp[1], c = Fp[2];
    float d = Fp[3], e = Fp[4], f = Fp[5];
    float g = Fp[6], h = Fp[7], i = Fp[8];

    // cofactors: F^{-T} = C/J, F^{-1} = C^T/J
    float C00 = fmaf(e, i, -f * h);
    float C01 = fmaf(f, g, -d * i);
    float C02 = fmaf(d, h, -e * g);
    float C10 = fmaf(c, h, -b * i);
    float C11 = fmaf(a, i, -c * g);
    float C12 = fmaf(b, g, -a * h);
    float C20 = fmaf(b, f, -c * e);
    float C21 = fmaf(c, d, -a * f);
    float C22 = fmaf(a, e, -b * d);

    float J   = a * C00 + b * C01 + c * C02;
    float rJ  = __frcp_rn(J);
    float lnJ = __logf(J);

    float s = (LAM * lnJ - MU) * rJ;
    float P00 = fmaf(s, C00, MU * a);
    float P01 = fmaf(s, C01, MU * b);
    float P02 = fmaf(s, C02, MU * c);
    float P10 = fmaf(s, C10, MU * d);
    float P11 = fmaf(s, C11, MU * e);
    float P12 = fmaf(s, C12, MU * f);
    float P20 = fmaf(s, C20, MU * g);
    float P21 = fmaf(s, C21, MU * h);
    float P22 = fmaf(s, C22, MU * i);

    // Finv = C^T/J
    float I00 = C00 * rJ, I01 = C10 * rJ, I02 = C20 * rJ;
    float I10 = C01 * rJ, I11 = C11 * rJ, I12 = C21 * rJ;
    float I20 = C02 * rJ, I21 = C12 * rJ, I22 = C22 * rJ;

    float M00 = I00*P00 + I01*P10 + I02*P20;
    float M01 = I00*P01 + I01*P11 + I02*P21;
    float M02 = I00*P02 + I01*P12 + I02*P22;
    float M10 = I10*P00 + I11*P10 + I12*P20;
    float M11 = I10*P01 + I11*P11 + I12*P21;
    float M12 = I10*P02 + I11*P12 + I12*P22;
    float M20 = I20*P00 + I21*P10 + I22*P20;
    float M21 = I20*P01 + I21*P11 + I22*P21;
    float M22 = I20*P02 + I21*P11 * 0.0f + I22*P22;  // placeholder (fixed below)

    // correct M22 (avoid accidental typo path)
    M22 = I20*P02 + I21*P12 + I22*P22;

    float S01 = 0.5f * (M01 + M10);
    float S02 = 0.5f * (M02 + M20);
    float S12 = 0.5f * (M12 + M21);

    float T00 = P00*a + P01*b + P02*c;
    float T01 = P00*d + P01*e + P02*f;
    float T02 = P00*g + P01*h + P02*i;
    float T10 = P10*a + P11*b + P12*c;
    float T11 = P10*d + P11*e + P12*f;
    float T12 = P10*g + P11*h + P12*i;
    float T20 = P20*a + P21*b + P22*c;
    float T21 = P20*d + P21*e + P22*f;
    float T22 = P20*g + P21*h + P22*i;

    o1[0] = P00; o1[1] = P01; o1[2] = P02;
    o1[3] = P10; o1[4] = P11; o1[5] = P12;
    o1[6] = P20; o1[7] = P21; o1[8] = P22;

    o2[0] = M00; o2[1] = S01; o2[2] = S02;
    o2[3] = S01; o2[4] = M11; o2[5] = S12;
    o2[6] = S02; o2[7] = S12; o2[8] = M22;

    float G01 = 0.5f * (T01 + T10) * rJ;
    float G02 = 0.5f * (T02 + T20) * rJ;
    float G12 = 0.5f * (T12 + T21) * rJ;
    o3[0] = T00 * rJ; o3[1] = G01;      o3[2] = G02;
    o3[3] = G01;      o3[4] = T11 * rJ; o3[5] = G12;
    o3[6] = G02;      o3[7] = G12;      o3[8] = T22 * rJ;
}

__device__ __forceinline__ void do_subtile(const float* __restrict__ sIn,
                                           float* __restrict__ sOut,
                                           int lane)
{
    float Fp[9], o1[9], o2[9], o3[9];
    #pragma unroll
    for (int k = 0; k < 9; k++) Fp[k] = sIn[lane * 9 + k];

    compute_point(Fp, o1, o2, o3);

    #pragma unroll
    for (int k = 0; k < 9; k++) {
        sOut[lane * 9 + k]       = o1[k];
        sOut[288 + lane * 9 + k] = o2[k];
        sOut[576 + lane * 9 + k] = o3[k];
    }
}

__device__ __forceinline__ void flush_subtile(const float* __restrict__ sOut,
                                              float* __restrict__ out,
                                              size_t nn, long base, int lane)
{
    #pragma unroll
    for (int r = 0; r < 3; r++) {
        float4* dst = (float4*)(out + r * nn + (size_t)base * 9);
        const float4* q = (const float4*)(sOut + r * 288);
        __stcs(dst + lane,      q[lane]);
        __stcs(dst + lane + 32, q[lane + 32]);
        if (lane < 8) __stcs(dst + lane + 64, q[lane + 64]);
    }
}

__global__ __launch_bounds__(BS, 10)
void hyper_kernel(const float* __restrict__ Fin,
                  float* __restrict__ out,
                  int n)
{
    __shared__ __align__(16) float sIn[WPB][2][288];     // double-buffered input
    __shared__ __align__(16) float sOut[WPB][3 * 288];   // staged outputs

    const int warp = threadIdx.x >> 5;
    const int lane = threadIdx.x & 31;
    const long baseA = (long)blockIdx.x * (BS * 2) + warp * 64;  // 64 pts/warp
    const long baseB = baseA + 32;
    const size_t nn = (size_t)n * 9;

    float* sO = sOut[warp];

    if (baseA + 64 <= n) {
        const float4* srcA = (const float4*)(Fin + (size_t)baseA * 9);
        const float4* srcB = (const float4*)(Fin + (size_t)baseB * 9);
        uint32_t dA = smem_u32(sIn[warp][0]);
        uint32_t dB = smem_u32(sIn[warp][1]);

        // issue ALL prefetches up-front: 4.5 cp.async/lane in flight
        cp_async16(dA + lane * 16,         srcA + lane);
        cp_async16(dA + (lane + 32) * 16,  srcA + lane + 32);
        if (lane < 8) cp_async16(dA + (lane + 64) * 16, srcA + lane + 64);
        cp_commit();
        cp_async16(dB + lane * 16,         srcB + lane);
        cp_async16(dB + (lane + 32) * 16,  srcB + lane + 32);
        if (lane < 8) cp_async16(dB + (lane + 64) * 16, srcB + lane + 64);
        cp_commit();

        // ---- sub-tile A ----
        cp_wait1();          // A landed (B may still be in flight)
        __syncwarp();
        do_subtile(sIn[warp][0], sO, lane);
        __syncwarp();
        flush_subtile(sO, out, nn, baseA, lane);

        // ---- sub-tile B ----
        cp_wait0();          // B landed
        __syncwarp();        // also guards sOut reuse (flush reads done)
        do_subtile(sIn[warp][1], sO, lane);
        __syncwarp();
        flush_subtile(sO, out, nn, baseB, lane);
    } else {
        // ---- tail: scalar guarded path ----
        #pragma unroll
        for (int s = 0; s < 2; s++) {
            long idx = baseA + s * 32 + lane;
            if (idx < n) {
                float Fp[9], o1[9], o2[9], o3[9];
                #pragma unroll
                for (int k = 0; k < 9; k++) Fp[k] = Fin[(size_t)idx * 9 + k];
                compute_point(Fp, o1, o2, o3);
                #pragma unroll
                for (int k = 0; k < 9; k++) {
                    out[(size_t)idx * 9 + k]          = o1[k];
                    out[nn + (size_t)idx * 9 + k]     = o2[k];
                    out[2 * nn + (size_t)idx * 9 + k] = o3[k];
                }
            }
        }
    }
}

extern "C" void kernel_launch(void* const* d_in, const int* in_sizes, int n_in,
                              void* d_out, int out_size)
{
    const float* F = (const float*)d_in[0];
    float* out = (float*)d_out;
    int n = in_sizes[0] / 9;

    int pts_per_block = BS * 2;
    int blocks = (n + pts_per_block - 1) / pts_per_block;
    hyper_kernel<<<blocks, BS>>>(F, out, n);
}

// round 8
// speedup vs baseline: 1.1790x; 1.0104x over previous
#include <cuda_runtime.h>
#include <cstdint>

// Hyperelasticity: closed-form Neo-Hookean stress.
// PK1 = MU*F + (LAM*lnJ - MU)*F^{-T};  PK2 = sym(F^{-1} PK1);  sig = sym(PK1 F^T)/J
//
// Warp-autonomous, 64 points/warp in two sub-tiles, double-buffered cp.async
// input prefetch. Output staged through a SINGLE reused 288-float per-warp
// buffer (3 region rounds) to cut smem and raise occupancy; regs capped via
// launch_bounds(128,12). Streaming stores.
#define MU  1.0f
#define LAM 1.0f
#define BS  128
#define WPB (BS / 32)

__device__ __forceinline__ uint32_t smem_u32(const void* p) {
    return (uint32_t)__cvta_generic_to_shared(p);
}
__device__ __forceinline__ void cp_async16(uint32_t dst, const void* src) {
    asm volatile("cp.async.cg.shared.global [%0], [%1], 16;\n" :: "r"(dst), "l"(src));
}
__device__ __forceinline__ void cp_commit() { asm volatile("cp.async.commit_group;\n"); }
__device__ __forceinline__ void cp_wait1()  { asm volatile("cp.async.wait_group 1;\n" ::: "memory"); }
__device__ __forceinline__ void cp_wait0()  { asm volatile("cp.async.wait_group 0;\n" ::: "memory"); }

__device__ __forceinline__ void compute_point(const float* __restrict__ Fp,
                                              float* __restrict__ o1,
                                              float* __restrict__ o2,
                                              float* __restrict__ o3)
{
    float a = Fp[0], b = Fp[1], c = Fp[2];
    float d = Fp[3], e = Fp[4], f = Fp[5];
    float g = Fp[6], h = Fp[7], i = Fp[8];

    // cofactors: F^{-T} = C/J, F^{-1} = C^T/J
    float C00 = fmaf(e, i, -f * h);
    float C01 = fmaf(f, g, -d * i);
    float C02 = fmaf(d, h, -e * g);
    float C10 = fmaf(c, h, -b * i);
    float C11 = fmaf(a, i, -c * g);
    float C12 = fmaf(b, g, -a * h);
    float C20 = fmaf(b, f, -c * e);
    float C21 = fmaf(c, d, -a * f);
    float C22 = fmaf(a, e, -b * d);

    float J   = a * C00 + b * C01 + c * C02;
    float rJ  = __frcp_rn(J);
    float lnJ = __logf(J);

    float s = (LAM * lnJ - MU) * rJ;
    float P00 = fmaf(s, C00, MU * a);
    float P01 = fmaf(s, C01, MU * b);
    float P02 = fmaf(s, C02, MU * c);
    float P10 = fmaf(s, C10, MU * d);
    float P11 = fmaf(s, C11, MU * e);
    float P12 = fmaf(s, C12, MU * f);
    float P20 = fmaf(s, C20, MU * g);
    float P21 = fmaf(s, C21, MU * h);
    float P22 = fmaf(s, C22, MU * i);

    // Finv = C^T/J
    float I00 = C00 * rJ, I01 = C10 * rJ, I02 = C20 * rJ;
    float I10 = C01 * rJ, I11 = C11 * rJ, I12 = C21 * rJ;
    float I20 = C02 * rJ, I21 = C12 * rJ, I22 = C22 * rJ;

    float M00 = I00*P00 + I01*P10 + I02*P20;
    float M01 = I00*P01 + I01*P11 + I02*P21;
    float M02 = I00*P02 + I01*P12 + I02*P22;
    float M10 = I10*P00 + I11*P10 + I12*P20;
    float M11 = I10*P01 + I11*P11 + I12*P21;
    float M12 = I10*P02 + I11*P12 + I12*P22;
    float M20 = I20*P00 + I21*P10 + I22*P20;
    float M21 = I20*P01 + I21*P11 + I22*P21;
    float M22 = I20*P02 + I21*P12 + I22*P22;

    float S01 = 0.5f * (M01 + M10);
    float S02 = 0.5f * (M02 + M20);
    float S12 = 0.5f * (M12 + M21);

    float T00 = P00*a + P01*b + P02*c;
    float T01 = P00*d + P01*e + P02*f;
    float T02 = P00*g + P01*h + P02*i;
    float T10 = P10*a + P11*b + P12*c;
    float T11 = P10*d + P11*e + P12*f;
    float T12 = P10*g + P11*h + P12*i;
    float T20 = P20*a + P21*b + P22*c;
    float T21 = P20*d + P21*e + P22*f;
    float T22 = P20*g + P21*h + P22*i;

    o1[0] = P00; o1[1] = P01; o1[2] = P02;
    o1[3] = P10; o1[4] = P11; o1[5] = P12;
    o1[6] = P20; o1[7] = P21; o1[8] = P22;

    o2[0] = M00; o2[1] = S01; o2[2] = S02;
    o2[3] = S01; o2[4] = M11; o2[5] = S12;
    o2[6] = S02; o2[7] = S12; o2[8] = M22;

    float G01 = 0.5f * (T01 + T10) * rJ;
    float G02 = 0.5f * (T02 + T20) * rJ;
    float G12 = 0.5f * (T12 + T21) * rJ;
    o3[0] = T00 * rJ; o3[1] = G01;      o3[2] = G02;
    o3[3] = G01;      o3[4] = T11 * rJ; o3[5] = G12;
    o3[6] = G02;      o3[7] = G12;      o3[8] = T22 * rJ;
}

// stage one 9-float region into the shared buffer, flush it coalesced
__device__ __forceinline__ void stage_flush(float* __restrict__ sBuf,
                                            const float* __restrict__ o,
                                            float* __restrict__ dst_f,
                                            int lane)
{
    #pragma unroll
    for (int k = 0; k < 9; k++) sBuf[lane * 9 + k] = o[k];
    __syncwarp();
    float4* dst = (float4*)dst_f;
    const float4* q = (const float4*)sBuf;
    __stcs(dst + lane,      q[lane]);
    __stcs(dst + lane + 32, q[lane + 32]);
    if (lane < 8) __stcs(dst + lane + 64, q[lane + 64]);
    __syncwarp();
}

__device__ __forceinline__ void do_subtile(const float* __restrict__ sIn,
                                           float* __restrict__ sBuf,
                                           float* __restrict__ out,
                                           size_t nn, long base, int lane)
{
    float Fp[9], o1[9], o2[9], o3[9];
    #pragma unroll
    for (int k = 0; k < 9; k++) Fp[k] = sIn[lane * 9 + k];

    compute_point(Fp, o1, o2, o3);

    stage_flush(sBuf, o1, out + (size_t)base * 9,          lane);
    stage_flush(sBuf, o2, out + nn + (size_t)base * 9,     lane);
    stage_flush(sBuf, o3, out + 2 * nn + (size_t)base * 9, lane);
}

__global__ __launch_bounds__(BS, 12)
void hyper_kernel(const float* __restrict__ Fin,
                  float* __restrict__ out,
                  int n)
{
    __shared__ __align__(16) float sIn[WPB][2][288];   // double-buffered input (9 KB)
    __shared__ __align__(16) float sOut[WPB][288];     // reused output buffer (4.5 KB)

    const int warp = threadIdx.x >> 5;
    const int lane = threadIdx.x & 31;
    const long baseA = (long)blockIdx.x * (BS * 2) + warp * 64;  // 64 pts/warp
    const long baseB = baseA + 32;
    const size_t nn = (size_t)n * 9;

    if (baseA + 64 <= n) {
        const float4* srcA = (const float4*)(Fin + (size_t)baseA * 9);
        const float4* srcB = (const float4*)(Fin + (size_t)baseB * 9);
        uint32_t dA = smem_u32(sIn[warp][0]);
        uint32_t dB = smem_u32(sIn[warp][1]);

        // issue ALL prefetches up-front: 4.5 cp.async/lane in flight
        cp_async16(dA + lane * 16,         srcA + lane);
        cp_async16(dA + (lane + 32) * 16,  srcA + lane + 32);
        if (lane < 8) cp_async16(dA + (lane + 64) * 16, srcA + lane + 64);
        cp_commit();
        cp_async16(dB + lane * 16,         srcB + lane);
        cp_async16(dB + (lane + 32) * 16,  srcB + lane + 32);
        if (lane < 8) cp_async16(dB + (lane + 64) * 16, srcB + lane + 64);
        cp_commit();

        // ---- sub-tile A ----
        cp_wait1();
        __syncwarp();
        do_subtile(sIn[warp][0], sOut[warp], out, nn, baseA, lane);

        // ---- sub-tile B ----
        cp_wait0();
        __syncwarp();
        do_subtile(sIn[warp][1], sOut[warp], out, nn, baseB, lane);
    } else {
        // ---- tail: scalar guarded path ----
        #pragma unroll
        for (int s = 0; s < 2; s++) {
            long idx = baseA + s * 32 + lane;
            if (idx < n) {
                float Fp[9], o1[9], o2[9], o3[9];
                #pragma unroll
                for (int k = 0; k < 9; k++) Fp[k] = Fin[(size_t)idx * 9 + k];
                compute_point(Fp, o1, o2, o3);
                #pragma unroll
                for (int k = 0; k < 9; k++) {
                    out[(size_t)idx * 9 + k]          = o1[k];
                    out[nn + (size_t)idx * 9 + k]     = o2[k];
                    out[2 * nn + (size_t)idx * 9 + k] = o3[k];
                }
            }
        }
    }
}

extern "C" void kernel_launch(void* const* d_in, const int* in_sizes, int n_in,
                              void* d_out, int out_size)
{
    const float* F = (const float*)d_in[0];
    float* out = (float*)d_out;
    int n = in_sizes[0] / 9;

    int pts_per_block = BS * 2;
    int blocks = (n + pts_per_block - 1) / pts_per_block;
    hyper_kernel<<<blocks, BS>>>(F, out, n);
}